// round 15
// baseline (speedup 1.0000x reference)
#include <cuda_runtime.h>
#include <math.h>
#include <stdint.h>

#define B 64
#define S 2048
#define E 1024
#define H 512
#define EMB 256
#define V 50257
#define BS (B*S)

// ---------------- device scratch (no allocations allowed) ----------------
__device__ float g_energy[BS];        // attn weights (written by softmax)
__device__ float g_epart[2*BS];       // energy partials per col-block
__device__ float g_ws_app[B*H];
__device__ float g_context[B*E];
__device__ float g_embed[B*EMB];
__device__ float g_gates[B*4*H];
__device__ float g_ht[B*H];
__device__ float g_ct[B*H];
__device__ float g_logits[(size_t)B*V];
__device__ float g_pgen[B];
// whw pre-split, fragment-interleaved: per row 128 uint4; uint2 slot j of group g
// holds (bf16x2 of k-pair g*8+j, bf16x2 of k-pair g*8+j+4). hi and lo separate.
__device__ uint4 g_wh[(size_t)H*128];
__device__ uint4 g_wl[(size_t)H*128];

// ---------------- helpers ----------------
__device__ __forceinline__ float sigmoidf_(float x){ return 1.f/(1.f+expf(-x)); }

// 2-way bf16 split of a pair of floats: hi = bf16x2(x0,x1), lo = bf16x2 of residuals.
__device__ __forceinline__ void split_bf16x2(float x0, float x1, uint32_t& hi, uint32_t& lo){
  asm("cvt.rn.bf16x2.f32 %0, %1, %2;" : "=r"(hi) : "f"(x1), "f"(x0));
  float h0 = __uint_as_float(hi << 16);
  float h1 = __uint_as_float(hi & 0xFFFF0000u);
  float l0 = x0 - h0;
  float l1 = x1 - h1;
  asm("cvt.rn.bf16x2.f32 %0, %1, %2;" : "=r"(lo) : "f"(l1), "f"(l0));
}

__device__ __forceinline__ void mma_bf16(float* c, const uint32_t* a, uint32_t b0, uint32_t b1){
  asm volatile("mma.sync.aligned.m16n8k16.row.col.f32.bf16.bf16.f32 "
    "{%0,%1,%2,%3}, {%4,%5,%6,%7}, {%8,%9}, {%0,%1,%2,%3};"
    : "+f"(c[0]),"+f"(c[1]),"+f"(c[2]),"+f"(c[3])
    : "r"(a[0]),"r"(a[1]),"r"(a[2]),"r"(a[3]),"r"(b0),"r"(b1));
}
__device__ __forceinline__ uint32_t smem_u32(const void* p){
  return (uint32_t)__cvta_generic_to_shared(p);
}
__device__ __forceinline__ void cp16(uint32_t s, const void* g){
  asm volatile("cp.async.cg.shared.global [%0], [%1], 16;" :: "r"(s), "l"(g));
}

// ---------------- kernels ----------------
// pre-split whw into fragment-interleaved hi/lo arrays
__global__ void conv_whw_kernel(const float* __restrict__ whw){
  int idx0 = blockIdx.x*blockDim.x + threadIdx.x;
  int stride = gridDim.x*blockDim.x;
  for (int idx=idx0; idx<H*64; idx+=stride){
    int r = idx>>6, g = idx&63;       // group g = 16 consecutive k
    const float4* src = (const float4*)&whw[(size_t)r*E + g*16];
    float4 v0=src[0], v1=src[1], v2=src[2], v3=src[3];
    uint32_t h[8], l[8];
    split_bf16x2(v0.x,v0.y,h[0],l[0]);
    split_bf16x2(v0.z,v0.w,h[1],l[1]);
    split_bf16x2(v1.x,v1.y,h[2],l[2]);
    split_bf16x2(v1.z,v1.w,h[3],l[3]);
    split_bf16x2(v2.x,v2.y,h[4],l[4]);
    split_bf16x2(v2.z,v2.w,h[5],l[5]);
    split_bf16x2(v3.x,v3.y,h[6],l[6]);
    split_bf16x2(v3.z,v3.w,h[7],l[7]);
    size_t o = (size_t)r*128 + g*2;
    g_wh[o  ] = make_uint4(h[0],h[4],h[1],h[5]);   // slots j=0,1 (pairs (0,4),(1,5))
    g_wh[o+1] = make_uint4(h[2],h[6],h[3],h[7]);   // slots j=2,3
    g_wl[o  ] = make_uint4(l[0],l[4],l[1],l[5]);
    g_wl[o+1] = make_uint4(l[2],l[6],l[3],l[7]);
  }
}

// ws_app[b,h] = h0[b]·attn_ws_w[h] + attn_ws_b[h]
__global__ void ws_app_kernel(const float* __restrict__ h0,
                              const float* __restrict__ wsw,
                              const float* __restrict__ wsb){
  int b = blockIdx.x;
  __shared__ float hs[H];
  for (int k=threadIdx.x;k<H;k+=blockDim.x) hs[k]=h0[b*H+k];
  __syncthreads();
  for (int h=threadIdx.x; h<H; h+=blockDim.x){
    const float4* wr = (const float4*)&wsw[(size_t)h*H];
    float s=0.f;
    #pragma unroll 4
    for (int k=0;k<H/4;k++){
      float4 w = wr[k];
      s += w.x*hs[4*k] + w.y*hs[4*k+1] + w.z*hs[4*k+2] + w.w*hs[4*k+3];
    }
    g_ws_app[b*H+h] = s + wsb[h];
  }
}

__global__ void embed_kernel(const int* __restrict__ dec_input, const float* __restrict__ table){
  int b=blockIdx.x;
  int tok = dec_input[b];
  g_embed[b*EMB + threadIdx.x] = table[(size_t)tok*EMB + threadIdx.x];
}

// ---------------- energy GEMM ----------------
// epart[cb][b,s] = sum over 256-col tile cb of attn_v[h]*tanh(enc·whw + whb + ws_app)
// M=131072, N=512, K=1024; 2-way bf16 split, 3 product passes, m16n8k16.
// Block 128x256, 512 threads, 16 warps (4x4), warp tile 32x64, kb=32.
// hi/lo in SEPARATE smem arrays, fragment-interleaved (uint2 = pairs p,p+4):
// one LDS.64 per single-precision B fragment; 3-pass schedule breaks acc chains.
// Row stride 80B: conflict-free LDS.64, 16B-aligned cp.async.
#define EG_AH   0u          // [2][128][10] uint2 : 20480
#define EG_AL   20480u      // [2][128][10] uint2 : 20480
#define EG_BH   40960u      // [2][256][10] uint2 : 40960
#define EG_BL   81920u      // [2][256][10] uint2 : 40960
#define EG_RED  122880u     // 128 floats
#define EG_SMEM 123392u

__global__ void __launch_bounds__(512,1) energy_gemm_kernel(
    const float* __restrict__ enc, const float* __restrict__ whb,
    const float* __restrict__ attn_v)
{
  extern __shared__ char smem[];
  const uint32_t sbase = smem_u32(smem);
  float* red = (float*)(smem + EG_RED);
  const int tid=threadIdx.x, lane=tid&31, wid=tid>>5;
  const int col0 = blockIdx.x*256;      // h columns
  const int row0 = blockIdx.y*128;      // seq rows
  const int warpM = wid>>2, warpN = wid&3;   // 4 x 4 warps, warp tile 32x64
  float acc[2][8][4];
  #pragma unroll
  for (int a=0;a<2;a++)
    #pragma unroll
    for(int n=0;n<8;n++)
      #pragma unroll
      for(int c=0;c<4;c++) acc[a][n][c]=0.f;

  // A prefetch geometry: 2 float4 per thread of the 128x32 fp32 tile
  int prow[2], pc4[2];
  #pragma unroll
  for (int i=0;i<2;i++){ int ff=tid+i*512; prow[i]=ff>>3; pc4[i]=(ff&7)*4; }
  float4 pa[2];
  #pragma unroll
  for (int i=0;i<2;i++)
    pa[i] = *(const float4*)&enc[(size_t)(row0+prow[i])*E + pc4[i]];

  // byte offset of pair p within a row of one chunk (interleaved layout)
  auto poff = [](int p){ return (uint32_t)((((p>>3)*4 + (p&3))<<3) + (((p>>2)&1)<<2)); };

  auto fillA = [&](int stage){
    #pragma unroll
    for (int i=0;i<2;i++){
      int r = prow[i], p = pc4[i]>>1;     // pairs p, p+1 (p even)
      uint32_t h0,l0,h1,l1;
      split_bf16x2(pa[i].x, pa[i].y, h0, l0);
      split_bf16x2(pa[i].z, pa[i].w, h1, l1);
      uint32_t baseH = (uint32_t)(EG_AH + stage*10240u + r*80u);
      uint32_t baseL = (uint32_t)(EG_AL + stage*10240u + r*80u);
      *(uint32_t*)(smem + baseH + poff(p  )) = h0;
      *(uint32_t*)(smem + baseH + poff(p+1)) = h1;
      *(uint32_t*)(smem + baseL + poff(p  )) = l0;
      *(uint32_t*)(smem + baseL + poff(p+1)) = l1;
    }
  };
  auto issueB = [&](int stage, int chunk){
    #pragma unroll
    for (int i=0;i<2;i++){
      int ci = i*512 + tid;
      int r = ci>>2, c = ci&3;
      uint32_t dst = sbase + EG_BH + (uint32_t)stage*20480u + (uint32_t)(r*80 + c*16);
      cp16(dst, &g_wh[(size_t)(col0+r)*128 + chunk*4 + c]);
    }
    #pragma unroll
    for (int i=0;i<2;i++){
      int ci = i*512 + tid;
      int r = ci>>2, c = ci&3;
      uint32_t dst = sbase + EG_BL + (uint32_t)stage*20480u + (uint32_t)(r*80 + c*16);
      cp16(dst, &g_wl[(size_t)(col0+r)*128 + chunk*4 + c]);
    }
    asm volatile("cp.async.commit_group;" ::: "memory");
  };

  const int NCHUNK = E/32;
  // prologue
  issueB(0, 0);
  fillA(0);
  #pragma unroll
  for (int i=0;i<2;i++)
    pa[i] = *(const float4*)&enc[(size_t)(row0+prow[i])*E + 32 + pc4[i]];
  asm volatile("cp.async.wait_group 0;" ::: "memory");
  __syncthreads();

  for (int chunk=0; chunk<NCHUNK; chunk++){
    int s = chunk&1;
    if (chunk+1 < NCHUNK){
      issueB(s^1, chunk+1);
      fillA(s^1);
      if (chunk+2 < NCHUNK){
        int kn = (chunk+2)*32;
        #pragma unroll
        for (int i=0;i<2;i++)
          pa[i] = *(const float4*)&enc[(size_t)(row0+prow[i])*E + kn + pc4[i]];
      }
    }
    const char* AH = smem + EG_AH + s*10240u;
    const char* AL = smem + EG_AL + s*10240u;
    const char* BH = smem + EG_BH + s*20480u;
    const char* BL = smem + EG_BL + s*20480u;
    #pragma unroll
    for (int kstep=0;kstep<2;kstep++){
      const uint32_t q8 = (uint32_t)((kstep*4 + (lane&3))<<3);
      uint32_t ah[2][4], al[2][4];
      #pragma unroll
      for (int mf=0;mf<2;mf++){
        int r = warpM*32 + (lane>>2) + mf*16;
        uint2 h0 = *(const uint2*)(AH + r*80 + q8);
        uint2 h1 = *(const uint2*)(AH + (r+8)*80 + q8);
        ah[mf][0]=h0.x; ah[mf][1]=h1.x; ah[mf][2]=h0.y; ah[mf][3]=h1.y;
        uint2 l0 = *(const uint2*)(AL + r*80 + q8);
        uint2 l1 = *(const uint2*)(AL + (r+8)*80 + q8);
        al[mf][0]=l0.x; al[mf][1]=l1.x; al[mf][2]=l0.y; al[mf][3]=l1.y;
      }
      // pass 1: hi*hi (16 independent MMAs)
      #pragma unroll
      for (int nf=0;nf<8;nf++){
        int bn_ = warpN*64 + nf*8 + (lane>>2);
        uint2 b = *(const uint2*)(BH + bn_*80 + q8);
        mma_bf16(acc[0][nf], ah[0], b.x, b.y);
        mma_bf16(acc[1][nf], ah[1], b.x, b.y);
      }
      // pass 2: hi*lo
      #pragma unroll
      for (int nf=0;nf<8;nf++){
        int bn_ = warpN*64 + nf*8 + (lane>>2);
        uint2 b = *(const uint2*)(BL + bn_*80 + q8);
        mma_bf16(acc[0][nf], ah[0], b.x, b.y);
        mma_bf16(acc[1][nf], ah[1], b.x, b.y);
      }
      // pass 3: lo*hi
      #pragma unroll
      for (int nf=0;nf<8;nf++){
        int bn_ = warpN*64 + nf*8 + (lane>>2);
        uint2 b = *(const uint2*)(BH + bn_*80 + q8);
        mma_bf16(acc[0][nf], al[0], b.x, b.y);
        mma_bf16(acc[1][nf], al[1], b.x, b.y);
      }
    }
    if (chunk+1 < NCHUNK)
      asm volatile("cp.async.wait_group 0;" ::: "memory");
    __syncthreads();
  }

  if (tid<128) red[tid]=0.f;
  __syncthreads();
  const int b = row0 >> 11;   // 2048 rows per batch
  #pragma unroll
  for (int mf=0;mf<2;mf++){
    #pragma unroll
    for (int half=0; half<2; half++){
      float sum=0.f;
      #pragma unroll
      for (int nf=0;nf<8;nf++){
        #pragma unroll
        for (int cc=0;cc<2;cc++){
          int cidx = half*2 + cc;
          int h = col0 + warpN*64 + nf*8 + 2*(lane&3) + cc;
          float z = acc[mf][nf][cidx] + whb[h] + g_ws_app[b*H + h];
          sum += attn_v[h]*tanhf(z);
        }
      }
      int rl = warpM*32 + mf*16 + (lane>>2) + half*8;
      atomicAdd(&red[rl], sum);
    }
  }
  __syncthreads();
  if (tid<128) g_epart[blockIdx.x*BS + row0 + tid] = red[tid];
}

__global__ void zero_kernel(){
  int i = blockIdx.x*blockDim.x + threadIdx.x;
  int stride = gridDim.x*blockDim.x;
  for (int j=i;j<B*E;j+=stride)    g_context[j]=0.f;
  for (int j=i;j<B*4*H;j+=stride)  g_gates[j]=0.f;
}

__global__ void attn_softmax_kernel(){
  int b = blockIdx.x;
  __shared__ float sm[256];
  float m=-1e30f;
  for (int s=threadIdx.x;s<S;s+=256){
    float e = g_epart[b*S+s] + g_epart[BS + b*S+s];
    g_energy[b*S+s] = e;
    m=fmaxf(m,e);
  }
  sm[threadIdx.x]=m; __syncthreads();
  for (int o=128;o>0;o>>=1){ if(threadIdx.x<o) sm[threadIdx.x]=fmaxf(sm[threadIdx.x],sm[threadIdx.x+o]); __syncthreads(); }
  m = sm[0]; __syncthreads();
  float sum=0.f;
  for (int s=threadIdx.x;s<S;s+=256) sum+=expf(g_energy[b*S+s]-m);
  sm[threadIdx.x]=sum; __syncthreads();
  for (int o=128;o>0;o>>=1){ if(threadIdx.x<o) sm[threadIdx.x]+=sm[threadIdx.x+o]; __syncthreads(); }
  float inv = 1.f/sm[0];
  for (int s=threadIdx.x;s<S;s+=256) g_energy[b*S+s]=expf(g_energy[b*S+s]-m)*inv;
}

// context[b,e] += sum_{s in chunk} attn[b,s]*enc[b,s,e]
__global__ void context_kernel(const float* __restrict__ enc){
  int b = blockIdx.x;
  int s0 = blockIdx.y*128;
  __shared__ float at[128];
  for (int i=threadIdx.x;i<128;i+=256) at[i]=g_energy[b*S+s0+i];
  __syncthreads();
  float acc[4]={0.f,0.f,0.f,0.f};
  const float* base = enc + ((size_t)b*S + s0)*E;
  for (int s=0;s<128;s++){
    float a = at[s];
    const float* row = base + (size_t)s*E;
    #pragma unroll
    for (int j=0;j<4;j++) acc[j] += a*row[threadIdx.x + j*256];
  }
  #pragma unroll
  for (int j=0;j<4;j++) atomicAdd(&g_context[b*E + threadIdx.x + j*256], acc[j]);
}

// gates[b,n] += x[b]·Wih[n] + h0[b]·Whh[n], K=1792 split into 8 chunks of 224
__global__ void gates_kernel(const float* __restrict__ wih, const float* __restrict__ whh,
                             const float* __restrict__ h0){
  __shared__ float Xs[64][33];
  __shared__ float Ws[64][33];
  int tid=threadIdx.x;
  int n0 = blockIdx.x*64;
  int k0 = blockIdx.y*224;
  float acc[4][4];
  #pragma unroll
  for(int i=0;i<4;i++)
    #pragma unroll
    for(int j=0;j<4;j++) acc[i][j]=0.f;
  int tr = tid>>4, tc = tid&15;
  for (int kk=0;kk<224;kk+=32){
    int kb = k0+kk;
    #pragma unroll
    for (int i=0;i<8;i++){
      int idx = tid + i*256;
      int r = idx>>5, k = idx&31;
      int kg = kb+k;
      float x;
      if (kg<E) x = g_context[r*E+kg];
      else if (kg<E+EMB) x = g_embed[r*EMB + kg-E];
      else x = h0[r*H + kg-(E+EMB)];
      Xs[r][k]=x;
      float w = (kg<E+EMB) ? wih[(size_t)(n0+r)*(E+EMB) + kg]
                           : whh[(size_t)(n0+r)*H + (kg-(E+EMB))];
      Ws[r][k]=w;
    }
    __syncthreads();
    #pragma unroll
    for (int k=0;k<32;k++){
      float xv[4],wv[4];
      #pragma unroll
      for(int i=0;i<4;i++) xv[i]=Xs[tr*4+i][k];
      #pragma unroll
      for(int j=0;j<4;j++) wv[j]=Ws[tc*4+j][k];
      #pragma unroll
      for(int i=0;i<4;i++)
        #pragma unroll
        for(int j=0;j<4;j++) acc[i][j]+=xv[i]*wv[j];
    }
    __syncthreads();
  }
  #pragma unroll
  for(int i=0;i<4;i++)
    #pragma unroll
    for(int j=0;j<4;j++)
      atomicAdd(&g_gates[(tr*4+i)*(4*H) + n0 + tc*4 + j], acc[i][j]);
}

__global__ void lstm_kernel(const float* __restrict__ c0,
                            const float* __restrict__ b_ih, const float* __restrict__ b_hh,
                            float* __restrict__ out){
  int b=blockIdx.x, h=threadIdx.x;
  const float* g = &g_gates[b*4*H];
  float ig = g[h]       + b_ih[h]       + b_hh[h];
  float fg = g[H+h]     + b_ih[H+h]     + b_hh[H+h];
  float gg = g[2*H+h]   + b_ih[2*H+h]   + b_hh[2*H+h];
  float og = g[3*H+h]   + b_ih[3*H+h]   + b_hh[3*H+h];
  float c  = sigmoidf_(fg)*c0[b*H+h] + sigmoidf_(ig)*tanhf(gg);
  float ht = sigmoidf_(og)*tanhf(c);
  g_ht[b*H+h]=ht; g_ct[b*H+h]=c;
  out[(size_t)B*V + b*H + h] = ht;
  out[(size_t)B*V + (size_t)B*H + b*H + h] = c;
}

// logits[b,n] = ht[b]·vw[n] + vb[n], M=64 N=50257 K=512.
// 2-way bf16 split (in-kernel), 3 products, m16n8k16. Tile 64x128, kb=32, 8 warps (2x4).
__global__ __launch_bounds__(256) void logits_gemm_kernel(const float* __restrict__ vw,
                                                          const float* __restrict__ vb){
  __shared__ uint2 Ahl[64][18];
  __shared__ uint2 Bhl[128][18];
  const int tid=threadIdx.x, lane=tid&31, wid=tid>>5;
  const int col0 = blockIdx.x*128;
  const int warpM = wid>>2, warpN = wid&3;    // 2 x 4 warps, warp tile 32x32
  float acc[2][4][4];
  #pragma unroll
  for (int a=0;a<2;a++)
    #pragma unroll
    for(int n=0;n<4;n++)
      #pragma unroll
      for(int c=0;c<4;c++) acc[a][n][c]=0.f;

  for (int k0=0;k0<H;k0+=32){
    #pragma unroll
    for (int i=0;i<2;i++){
      int ff = tid + i*256;
      int r = ff>>3, c4 = (ff&7)*4;
      float4 v = *(const float4*)&g_ht[r*H + k0 + c4];
      uint32_t h,l;
      split_bf16x2(v.x, v.y, h, l); Ahl[r][(c4>>1)  ] = make_uint2(h,l);
      split_bf16x2(v.z, v.w, h, l); Ahl[r][(c4>>1)+1] = make_uint2(h,l);
    }
    #pragma unroll
    for (int i=0;i<4;i++){
      int ff = tid + i*256;
      int r = ff>>3, c4 = (ff&7)*4;
      int n = col0 + r;
      float4 v = (n<V) ? *(const float4*)&vw[(size_t)n*H + k0 + c4]
                       : make_float4(0.f,0.f,0.f,0.f);
      uint32_t h,l;
      split_bf16x2(v.x, v.y, h, l); Bhl[r][(c4>>1)  ] = make_uint2(h,l);
      split_bf16x2(v.z, v.w, h, l); Bhl[r][(c4>>1)+1] = make_uint2(h,l);
    }
    __syncthreads();
    #pragma unroll
    for (int kstep=0;kstep<2;kstep++){
      int ap = kstep*8 + (lane&3);
      uint32_t ah[2][4], al[2][4];
      int ar = warpM*32 + (lane>>2);
      #pragma unroll
      for (int mf=0;mf<2;mf++){
        int r = ar + mf*16;
        uint2 v0 = Ahl[r  ][ap  ];
        uint2 v1 = Ahl[r+8][ap  ];
        uint2 v2 = Ahl[r  ][ap+4];
        uint2 v3 = Ahl[r+8][ap+4];
        ah[mf][0]=v0.x; al[mf][0]=v0.y;
        ah[mf][1]=v1.x; al[mf][1]=v1.y;
        ah[mf][2]=v2.x; al[mf][2]=v2.y;
        ah[mf][3]=v3.x; al[mf][3]=v3.y;
      }
      // pass-ordered to break accumulator chains
      uint32_t bh[4][2], bl[4][2];
      #pragma unroll
      for (int nf=0;nf<4;nf++){
        int bn_ = warpN*32 + nf*8 + (lane>>2);
        uint2 B0 = Bhl[bn_][ap  ];
        uint2 B1 = Bhl[bn_][ap+4];
        bh[nf][0]=B0.x; bh[nf][1]=B1.x;
        bl[nf][0]=B0.y; bl[nf][1]=B1.y;
      }
      #pragma unroll
      for (int nf=0;nf<4;nf++){
        mma_bf16(acc[0][nf], ah[0], bh[nf][0], bh[nf][1]);
        mma_bf16(acc[1][nf], ah[1], bh[nf][0], bh[nf][1]);
      }
      #pragma unroll
      for (int nf=0;nf<4;nf++){
        mma_bf16(acc[0][nf], ah[0], bl[nf][0], bl[nf][1]);
        mma_bf16(acc[1][nf], ah[1], bl[nf][0], bl[nf][1]);
      }
      #pragma unroll
      for (int nf=0;nf<4;nf++){
        mma_bf16(acc[0][nf], al[0], bh[nf][0], bh[nf][1]);
        mma_bf16(acc[1][nf], al[1], bh[nf][0], bh[nf][1]);
      }
    }
    __syncthreads();
  }
  #pragma unroll
  for (int mf=0;mf<2;mf++)
    #pragma unroll
    for (int nf=0;nf<4;nf++)
      #pragma unroll
      for (int cidx=0;cidx<4;cidx++){
        int r = warpM*32 + mf*16 + (lane>>2) + (cidx>>1)*8;
        int n = col0 + warpN*32 + nf*8 + 2*(lane&3) + (cidx&1);
        if (n<V) g_logits[(size_t)r*V + n] = acc[mf][nf][cidx] + vb[n];
      }
}

__global__ void pgen_kernel(const float* __restrict__ whv, const float* __restrict__ wsv,
                            const float* __restrict__ wxv){
  int b=blockIdx.x;
  __shared__ float sm[256];
  float s=0.f;
  for (int e=threadIdx.x;e<E;e+=256) s+=g_context[b*E+e]*whv[e];
  for (int h=threadIdx.x;h<H;h+=256) s+=g_ht[b*H+h]*wsv[h];
  if (threadIdx.x<EMB) s+=g_embed[b*EMB+threadIdx.x]*wxv[threadIdx.x];
  sm[threadIdx.x]=s; __syncthreads();
  for (int o=128;o>0;o>>=1){ if(threadIdx.x<o) sm[threadIdx.x]+=sm[threadIdx.x+o]; __syncthreads(); }
  if (threadIdx.x==0) g_pgen[b]=1.f/(1.f+expf(-sm[0]));
}

__global__ void vocab_out_kernel(float* __restrict__ out){
  int b=blockIdx.x;
  __shared__ float sm[256];
  const float* l = &g_logits[(size_t)b*V];
  float m=-1e30f;
  for (int v=threadIdx.x;v<V;v+=256) m=fmaxf(m,l[v]);
  sm[threadIdx.x]=m; __syncthreads();
  for (int o=128;o>0;o>>=1){ if(threadIdx.x<o) sm[threadIdx.x]=fmaxf(sm[threadIdx.x],sm[threadIdx.x+o]); __syncthreads(); }
  m=sm[0]; __syncthreads();
  float s=0.f;
  for (int v=threadIdx.x;v<V;v+=256) s+=expf(l[v]-m);
  sm[threadIdx.x]=s; __syncthreads();
  for (int o=128;o>0;o>>=1){ if(threadIdx.x<o) sm[threadIdx.x]+=sm[threadIdx.x+o]; __syncthreads(); }
  float scale = g_pgen[b]/sm[0];
  for (int v=threadIdx.x;v<V;v+=256) out[(size_t)b*V+v]=expf(l[v]-m)*scale;
}

__global__ void scatter_kernel(const int* __restrict__ enc_inputs, float* __restrict__ out){
  int b=blockIdx.x;
  float om = 1.f - g_pgen[b];
  for (int s=threadIdx.x;s<S;s+=256){
    int tok = enc_inputs[b*S+s];
    atomicAdd(&out[(size_t)b*V+tok], om*g_energy[b*S+s]);
  }
}

// ---------------- launch ----------------
extern "C" void kernel_launch(void* const* d_in, const int* in_sizes, int n_in,
                              void* d_out, int out_size){
  const float* enc_out     = (const float*)d_in[0];
  const float* h0          = (const float*)d_in[1];
  const float* c0          = (const float*)d_in[2];
  const int*   dec_input   = (const int*)  d_in[3];
  const int*   enc_inputs  = (const int*)  d_in[4];
  const float* embed_table = (const float*)d_in[5];
  const float* attn_wh_w   = (const float*)d_in[6];
  const float* attn_wh_b   = (const float*)d_in[7];
  const float* attn_ws_w   = (const float*)d_in[8];
  const float* attn_ws_b   = (const float*)d_in[9];
  const float* attn_v      = (const float*)d_in[10];
  const float* lstm_w_ih   = (const float*)d_in[11];
  const float* lstm_w_hh   = (const float*)d_in[12];
  const float* lstm_b_ih   = (const float*)d_in[13];
  const float* lstm_b_hh   = (const float*)d_in[14];
  const float* wh_vec      = (const float*)d_in[15];
  const float* ws_vec      = (const float*)d_in[16];
  const float* wx_vec      = (const float*)d_in[17];
  const float* v_w         = (const float*)d_in[18];
  const float* v_b         = (const float*)d_in[19];
  float* out = (float*)d_out;

  // host-side attribute set (not a stream op; capture-safe)
  (void)cudaFuncSetAttribute(energy_gemm_kernel,
      cudaFuncAttributeMaxDynamicSharedMemorySize, EG_SMEM);

  conv_whw_kernel<<<128,256>>>(attn_wh_w);                                        // 0
  ws_app_kernel<<<B,256>>>(h0, attn_ws_w, attn_ws_b);                             // 1
  embed_kernel<<<B,256>>>(dec_input, embed_table);                                // 2
  energy_gemm_kernel<<<dim3(H/256, BS/128),512,EG_SMEM>>>(enc_out, attn_wh_b, attn_v); // 3 (profiled)
  zero_kernel<<<256,256>>>();                                                     // 4
  attn_softmax_kernel<<<B,256>>>();                                               // 5
  context_kernel<<<dim3(B,16),256>>>(enc_out);
  gates_kernel<<<dim3(32,8),256>>>(lstm_w_ih, lstm_w_hh, h0);
  lstm_kernel<<<B,H>>>(c0, lstm_b_ih, lstm_b_hh, out);
  logits_gemm_kernel<<<(V+127)/128,256>>>(v_w, v_b);
  pgen_kernel<<<B,256>>>(wh_vec, ws_vec, wx_vec);
  vocab_out_kernel<<<B,256>>>(out);
  scatter_kernel<<<B,256>>>(enc_inputs, out);
}

// round 16
// speedup vs baseline: 1.0862x; 1.0862x over previous
#include <cuda_runtime.h>
#include <math.h>
#include <stdint.h>

#define B 64
#define S 2048
#define E 1024
#define H 512
#define EMB 256
#define V 50257
#define BS (B*S)

// ---------------- device scratch (no allocations allowed) ----------------
__device__ float g_energy[BS];        // attn weights (written by softmax)
__device__ float g_epart[4*BS];       // energy partials per col-block
__device__ float g_ws_app[B*H];
__device__ float g_context[B*E];
__device__ float g_embed[B*EMB];
__device__ float g_gates[B*4*H];
__device__ float g_ht[B*H];
__device__ float g_ct[B*H];
__device__ float g_logits[(size_t)B*V];
__device__ float g_pgen[B];
// pre-split whw: each uint4 = (hi01, lo01, hi23, lo23) bf16x2 for 4 consecutive k
__device__ uint4 g_whw2[(size_t)H*E/4];

// ---------------- helpers ----------------
__device__ __forceinline__ float sigmoidf_(float x){ return 1.f/(1.f+expf(-x)); }

// 2-way bf16 split of a pair of floats: hi = bf16x2(x0,x1), lo = bf16x2 of residuals.
__device__ __forceinline__ void split_bf16x2(float x0, float x1, uint32_t& hi, uint32_t& lo){
  asm("cvt.rn.bf16x2.f32 %0, %1, %2;" : "=r"(hi) : "f"(x1), "f"(x0));
  float h0 = __uint_as_float(hi << 16);
  float h1 = __uint_as_float(hi & 0xFFFF0000u);
  float l0 = x0 - h0;
  float l1 = x1 - h1;
  asm("cvt.rn.bf16x2.f32 %0, %1, %2;" : "=r"(lo) : "f"(l1), "f"(l0));
}

__device__ __forceinline__ void mma_bf16(float* c, const uint32_t* a, uint32_t b0, uint32_t b1){
  asm volatile("mma.sync.aligned.m16n8k16.row.col.f32.bf16.bf16.f32 "
    "{%0,%1,%2,%3}, {%4,%5,%6,%7}, {%8,%9}, {%0,%1,%2,%3};"
    : "+f"(c[0]),"+f"(c[1]),"+f"(c[2]),"+f"(c[3])
    : "r"(a[0]),"r"(a[1]),"r"(a[2]),"r"(a[3]),"r"(b0),"r"(b1));
}
__device__ __forceinline__ uint32_t smem_u32(const void* p){
  return (uint32_t)__cvta_generic_to_shared(p);
}
__device__ __forceinline__ void cp16(uint32_t s, const void* g){
  asm volatile("cp.async.cg.shared.global [%0], [%1], 16;" :: "r"(s), "l"(g));
}

// ---------------- kernels ----------------
// pre-split whw only (4MB; reused by all CTAs)
__global__ void conv_whw_kernel(const float* __restrict__ whw){
  size_t i = (size_t)blockIdx.x*blockDim.x + threadIdx.x;
  size_t stride = (size_t)gridDim.x*blockDim.x;
  for (size_t j=i; j<(size_t)H*E/4; j+=stride){
    float4 v = ((const float4*)whw)[j];
    uint32_t h0,l0,h1,l1;
    split_bf16x2(v.x,v.y,h0,l0);
    split_bf16x2(v.z,v.w,h1,l1);
    g_whw2[j] = make_uint4(h0,l0,h1,l1);
  }
}

// ws_app[b,h] = h0[b]·attn_ws_w[h] + attn_ws_b[h]
__global__ void ws_app_kernel(const float* __restrict__ h0,
                              const float* __restrict__ wsw,
                              const float* __restrict__ wsb){
  int b = blockIdx.x;
  __shared__ float hs[H];
  for (int k=threadIdx.x;k<H;k+=blockDim.x) hs[k]=h0[b*H+k];
  __syncthreads();
  for (int h=threadIdx.x; h<H; h+=blockDim.x){
    const float4* wr = (const float4*)&wsw[(size_t)h*H];
    float s=0.f;
    #pragma unroll 4
    for (int k=0;k<H/4;k++){
      float4 w = wr[k];
      s += w.x*hs[4*k] + w.y*hs[4*k+1] + w.z*hs[4*k+2] + w.w*hs[4*k+3];
    }
    g_ws_app[b*H+h] = s + wsb[h];
  }
}

__global__ void embed_kernel(const int* __restrict__ dec_input, const float* __restrict__ table){
  int b=blockIdx.x;
  int tok = dec_input[b];
  g_embed[b*EMB + threadIdx.x] = table[(size_t)tok*EMB + threadIdx.x];
}

// ---------------- energy GEMM ----------------
// epart[cb][b,s] = sum over 128-col tile cb of attn_v[h]*tanh(enc·whw + whb + ws_app)
// M=131072, N=512, K=1024; 2-way bf16 split, 3 products, m16n8k16.
// Block tile 128x128, 256 threads, 8 warps (4x2), warp tile 32x64, kb=32.
// 2 CTAs/SM (launch_bounds(256,2), smem 82KB): independent pipelines overlap
// each other's barrier/drain windows on the tensor pipe.
#define EG_A    0u                     // [2][128][20] uint2 = 40960
#define EG_B    40960u                 // [2][128][20] uint2 = 40960
#define EG_RED  81920u                 // 128 floats
#define EG_SMEM 82432u

__global__ void __launch_bounds__(256,2) energy_gemm_kernel(
    const float* __restrict__ enc, const float* __restrict__ whb,
    const float* __restrict__ attn_v)
{
  extern __shared__ char smem[];
  const uint32_t sbase = smem_u32(smem);
  float* red = (float*)(smem + EG_RED);
  const int tid=threadIdx.x, lane=tid&31, wid=tid>>5;
  const int col0 = blockIdx.x*128;      // h columns
  const int row0 = blockIdx.y*128;      // seq rows
  const int warpM = wid>>1, warpN = wid&1;   // 4 x 2 warps, warp tile 32x64
  float acc[2][8][4];
  #pragma unroll
  for (int a=0;a<2;a++)
    #pragma unroll
    for(int n=0;n<8;n++)
      #pragma unroll
      for(int c=0;c<4;c++) acc[a][n][c]=0.f;

  // A prefetch geometry: 4 float4 per thread of the 128x32 fp32 tile
  int prow[4], pc4[4];
  #pragma unroll
  for (int i=0;i<4;i++){ int ff=tid+i*256; prow[i]=ff>>3; pc4[i]=(ff&7)*4; }
  float4 pa[4];
  #pragma unroll
  for (int i=0;i<4;i++)
    pa[i] = *(const float4*)&enc[(size_t)(row0+prow[i])*E + pc4[i]];

  auto fillA = [&](int stage){
    uint2 (*A)[20] = (uint2(*)[20])(smem + EG_A + (uint32_t)stage*20480u);
    #pragma unroll
    for (int i=0;i<4;i++){
      int r = prow[i], p = pc4[i]>>1;
      uint32_t h,l;
      split_bf16x2(pa[i].x, pa[i].y, h, l); A[r][p  ] = make_uint2(h,l);
      split_bf16x2(pa[i].z, pa[i].w, h, l); A[r][p+1] = make_uint2(h,l);
    }
  };
  auto issueB = [&](int stage, int kq0){   // kq0 in uint4 units (chunk*8)
    #pragma unroll
    for (int i=0;i<4;i++){
      int ci = i*256 + tid;
      int r = ci>>3, c = ci&7;
      uint32_t dst = sbase + EG_B + (uint32_t)stage*20480u + (uint32_t)(r*160 + c*16);
      cp16(dst, &g_whw2[(size_t)(col0+r)*(E/4) + kq0 + c]);
    }
    asm volatile("cp.async.commit_group;" ::: "memory");
  };

  const int NCHUNK = E/32;
  // prologue: stage 0 = chunk 0
  issueB(0, 0);
  fillA(0);
  // prefetch A chunk 1
  #pragma unroll
  for (int i=0;i<4;i++)
    pa[i] = *(const float4*)&enc[(size_t)(row0+prow[i])*E + 32 + pc4[i]];
  asm volatile("cp.async.wait_group 0;" ::: "memory");
  __syncthreads();

  for (int chunk=0; chunk<NCHUNK; chunk++){
    int s = chunk&1;
    // loop-top (post-barrier): prepare stage s^1 for chunk+1, overlapped with MMA below
    if (chunk+1 < NCHUNK){
      issueB(s^1, (chunk+1)*8);
      fillA(s^1);
      if (chunk+2 < NCHUNK){
        int kn = (chunk+2)*32;
        #pragma unroll
        for (int i=0;i<4;i++)
          pa[i] = *(const float4*)&enc[(size_t)(row0+prow[i])*E + kn + pc4[i]];
      }
    }
    uint2 (*Ahl)[20] = (uint2(*)[20])(smem + EG_A + (uint32_t)s*20480u);
    uint2 (*Bhl)[20] = (uint2(*)[20])(smem + EG_B + (uint32_t)s*20480u);
    #pragma unroll
    for (int kstep=0;kstep<2;kstep++){
      int ap = kstep*8 + (lane&3);
      uint32_t ah[2][4], al[2][4];
      int arb = warpM*32 + (lane>>2);
      #pragma unroll
      for (int mf=0;mf<2;mf++){
        int r = arb + mf*16;
        uint2 v0 = Ahl[r  ][ap  ];
        uint2 v1 = Ahl[r+8][ap  ];
        uint2 v2 = Ahl[r  ][ap+4];
        uint2 v3 = Ahl[r+8][ap+4];
        ah[mf][0]=v0.x; al[mf][0]=v0.y;
        ah[mf][1]=v1.x; al[mf][1]=v1.y;
        ah[mf][2]=v2.x; al[mf][2]=v2.y;
        ah[mf][3]=v3.x; al[mf][3]=v3.y;
      }
      #pragma unroll
      for (int nf=0;nf<8;nf++){
        int bn_ = warpN*64 + nf*8 + (lane>>2);
        uint2 B0 = Bhl[bn_][ap  ];
        uint2 B1 = Bhl[bn_][ap+4];
        #pragma unroll
        for (int mf=0;mf<2;mf++){
          mma_bf16(acc[mf][nf], ah[mf], B0.x, B1.x);   // hi*hi
          mma_bf16(acc[mf][nf], ah[mf], B0.y, B1.y);   // hi*lo
          mma_bf16(acc[mf][nf], al[mf], B0.x, B1.x);   // lo*hi
        }
      }
    }
    if (chunk+1 < NCHUNK)
      asm volatile("cp.async.wait_group 0;" ::: "memory");
    __syncthreads();
  }

  if (tid<128) red[tid]=0.f;
  __syncthreads();
  const int b = row0 >> 11;   // 2048 rows per batch
  #pragma unroll
  for (int mf=0;mf<2;mf++){
    #pragma unroll
    for (int half=0; half<2; half++){
      float sum=0.f;
      #pragma unroll
      for (int nf=0;nf<8;nf++){
        #pragma unroll
        for (int cc=0;cc<2;cc++){
          int cidx = half*2 + cc;
          int h = col0 + warpN*64 + nf*8 + 2*(lane&3) + cc;
          float z = acc[mf][nf][cidx] + whb[h] + g_ws_app[b*H + h];
          sum += attn_v[h]*tanhf(z);
        }
      }
      int rl = warpM*32 + mf*16 + (lane>>2) + half*8;
      atomicAdd(&red[rl], sum);
    }
  }
  __syncthreads();
  if (tid<128) g_epart[blockIdx.x*BS + row0 + tid] = red[tid];
}

__global__ void zero_kernel(){
  int i = blockIdx.x*blockDim.x + threadIdx.x;
  int stride = gridDim.x*blockDim.x;
  for (int j=i;j<B*E;j+=stride)    g_context[j]=0.f;
  for (int j=i;j<B*4*H;j+=stride)  g_gates[j]=0.f;
}

__global__ void attn_softmax_kernel(){
  int b = blockIdx.x;
  __shared__ float sm[256];
  float m=-1e30f;
  for (int s=threadIdx.x;s<S;s+=256){
    float e = g_epart[b*S+s] + g_epart[BS + b*S+s]
            + g_epart[2*BS + b*S+s] + g_epart[3*BS + b*S+s];
    g_energy[b*S+s] = e;
    m=fmaxf(m,e);
  }
  sm[threadIdx.x]=m; __syncthreads();
  for (int o=128;o>0;o>>=1){ if(threadIdx.x<o) sm[threadIdx.x]=fmaxf(sm[threadIdx.x],sm[threadIdx.x+o]); __syncthreads(); }
  m = sm[0]; __syncthreads();
  float sum=0.f;
  for (int s=threadIdx.x;s<S;s+=256) sum+=expf(g_energy[b*S+s]-m);
  sm[threadIdx.x]=sum; __syncthreads();
  for (int o=128;o>0;o>>=1){ if(threadIdx.x<o) sm[threadIdx.x]+=sm[threadIdx.x+o]; __syncthreads(); }
  float inv = 1.f/sm[0];
  for (int s=threadIdx.x;s<S;s+=256) g_energy[b*S+s]=expf(g_energy[b*S+s]-m)*inv;
}

// context[b,e] += sum_{s in chunk} attn[b,s]*enc[b,s,e]
__global__ void context_kernel(const float* __restrict__ enc){
  int b = blockIdx.x;
  int s0 = blockIdx.y*128;
  __shared__ float at[128];
  for (int i=threadIdx.x;i<128;i+=256) at[i]=g_energy[b*S+s0+i];
  __syncthreads();
  float acc[4]={0.f,0.f,0.f,0.f};
  const float* base = enc + ((size_t)b*S + s0)*E;
  for (int s=0;s<128;s++){
    float a = at[s];
    const float* row = base + (size_t)s*E;
    #pragma unroll
    for (int j=0;j<4;j++) acc[j] += a*row[threadIdx.x + j*256];
  }
  #pragma unroll
  for (int j=0;j<4;j++) atomicAdd(&g_context[b*E + threadIdx.x + j*256], acc[j]);
}

// gates[b,n] += x[b]·Wih[n] + h0[b]·Whh[n], K=1792 split into 8 chunks of 224
__global__ void gates_kernel(const float* __restrict__ wih, const float* __restrict__ whh,
                             const float* __restrict__ h0){
  __shared__ float Xs[64][33];
  __shared__ float Ws[64][33];
  int tid=threadIdx.x;
  int n0 = blockIdx.x*64;
  int k0 = blockIdx.y*224;
  float acc[4][4];
  #pragma unroll
  for(int i=0;i<4;i++)
    #pragma unroll
    for(int j=0;j<4;j++) acc[i][j]=0.f;
  int tr = tid>>4, tc = tid&15;
  for (int kk=0;kk<224;kk+=32){
    int kb = k0+kk;
    #pragma unroll
    for (int i=0;i<8;i++){
      int idx = tid + i*256;
      int r = idx>>5, k = idx&31;
      int kg = kb+k;
      float x;
      if (kg<E) x = g_context[r*E+kg];
      else if (kg<E+EMB) x = g_embed[r*EMB + kg-E];
      else x = h0[r*H + kg-(E+EMB)];
      Xs[r][k]=x;
      float w = (kg<E+EMB) ? wih[(size_t)(n0+r)*(E+EMB) + kg]
                           : whh[(size_t)(n0+r)*H + (kg-(E+EMB))];
      Ws[r][k]=w;
    }
    __syncthreads();
    #pragma unroll
    for (int k=0;k<32;k++){
      float xv[4],wv[4];
      #pragma unroll
      for(int i=0;i<4;i++) xv[i]=Xs[tr*4+i][k];
      #pragma unroll
      for(int j=0;j<4;j++) wv[j]=Ws[tc*4+j][k];
      #pragma unroll
      for(int i=0;i<4;i++)
        #pragma unroll
        for(int j=0;j<4;j++) acc[i][j]+=xv[i]*wv[j];
    }
    __syncthreads();
  }
  #pragma unroll
  for(int i=0;i<4;i++)
    #pragma unroll
    for(int j=0;j<4;j++)
      atomicAdd(&g_gates[(tr*4+i)*(4*H) + n0 + tc*4 + j], acc[i][j]);
}

__global__ void lstm_kernel(const float* __restrict__ c0,
                            const float* __restrict__ b_ih, const float* __restrict__ b_hh,
                            float* __restrict__ out){
  int b=blockIdx.x, h=threadIdx.x;
  const float* g = &g_gates[b*4*H];
  float ig = g[h]       + b_ih[h]       + b_hh[h];
  float fg = g[H+h]     + b_ih[H+h]     + b_hh[H+h];
  float gg = g[2*H+h]   + b_ih[2*H+h]   + b_hh[2*H+h];
  float og = g[3*H+h]   + b_ih[3*H+h]   + b_hh[3*H+h];
  float c  = sigmoidf_(fg)*c0[b*H+h] + sigmoidf_(ig)*tanhf(gg);
  float ht = sigmoidf_(og)*tanhf(c);
  g_ht[b*H+h]=ht; g_ct[b*H+h]=c;
  out[(size_t)B*V + b*H + h] = ht;
  out[(size_t)B*V + (size_t)B*H + b*H + h] = c;
}

// logits[b,n] = ht[b]·vw[n] + vb[n], M=64 N=50257 K=512.
// 2-way bf16 split (in-kernel), 3 products, m16n8k16. Tile 64x128, kb=32, 8 warps (2x4).
__global__ __launch_bounds__(256) void logits_gemm_kernel(const float* __restrict__ vw,
                                                          const float* __restrict__ vb){
  __shared__ uint2 Ahl[64][18];
  __shared__ uint2 Bhl[128][18];
  const int tid=threadIdx.x, lane=tid&31, wid=tid>>5;
  const int col0 = blockIdx.x*128;
  const int warpM = wid>>2, warpN = wid&3;    // 2 x 4 warps, warp tile 32x32
  float acc[2][4][4];
  #pragma unroll
  for (int a=0;a<2;a++)
    #pragma unroll
    for(int n=0;n<4;n++)
      #pragma unroll
      for(int c=0;c<4;c++) acc[a][n][c]=0.f;

  for (int k0=0;k0<H;k0+=32){
    #pragma unroll
    for (int i=0;i<2;i++){
      int ff = tid + i*256;
      int r = ff>>3, c4 = (ff&7)*4;
      float4 v = *(const float4*)&g_ht[r*H + k0 + c4];
      uint32_t h,l;
      split_bf16x2(v.x, v.y, h, l); Ahl[r][(c4>>1)  ] = make_uint2(h,l);
      split_bf16x2(v.z, v.w, h, l); Ahl[r][(c4>>1)+1] = make_uint2(h,l);
    }
    #pragma unroll
    for (int i=0;i<4;i++){
      int ff = tid + i*256;
      int r = ff>>3, c4 = (ff&7)*4;
      int n = col0 + r;
      float4 v = (n<V) ? *(const float4*)&vw[(size_t)n*H + k0 + c4]
                       : make_float4(0.f,0.f,0.f,0.f);
      uint32_t h,l;
      split_bf16x2(v.x, v.y, h, l); Bhl[r][(c4>>1)  ] = make_uint2(h,l);
      split_bf16x2(v.z, v.w, h, l); Bhl[r][(c4>>1)+1] = make_uint2(h,l);
    }
    __syncthreads();
    #pragma unroll
    for (int kstep=0;kstep<2;kstep++){
      int ap = kstep*8 + (lane&3);
      uint32_t ah[2][4], al[2][4];
      int ar = warpM*32 + (lane>>2);
      #pragma unroll
      for (int mf=0;mf<2;mf++){
        int r = ar + mf*16;
        uint2 v0 = Ahl[r  ][ap  ];
        uint2 v1 = Ahl[r+8][ap  ];
        uint2 v2 = Ahl[r  ][ap+4];
        uint2 v3 = Ahl[r+8][ap+4];
        ah[mf][0]=v0.x; al[mf][0]=v0.y;
        ah[mf][1]=v1.x; al[mf][1]=v1.y;
        ah[mf][2]=v2.x; al[mf][2]=v2.y;
        ah[mf][3]=v3.x; al[mf][3]=v3.y;
      }
      #pragma unroll
      for (int nf=0;nf<4;nf++){
        int bn_ = warpN*32 + nf*8 + (lane>>2);
        uint2 B0 = Bhl[bn_][ap  ];
        uint2 B1 = Bhl[bn_][ap+4];
        mma_bf16(acc[0][nf], ah[0], B0.x, B1.x);
        mma_bf16(acc[0][nf], ah[0], B0.y, B1.y);
        mma_bf16(acc[0][nf], al[0], B0.x, B1.x);
        mma_bf16(acc[1][nf], ah[1], B0.x, B1.x);
        mma_bf16(acc[1][nf], ah[1], B0.y, B1.y);
        mma_bf16(acc[1][nf], al[1], B0.x, B1.x);
      }
    }
    __syncthreads();
  }
  #pragma unroll
  for (int mf=0;mf<2;mf++)
    #pragma unroll
    for (int nf=0;nf<4;nf++)
      #pragma unroll
      for (int cidx=0;cidx<4;cidx++){
        int r = warpM*32 + mf*16 + (lane>>2) + (cidx>>1)*8;
        int n = col0 + warpN*32 + nf*8 + 2*(lane&3) + (cidx&1);
        if (n<V) g_logits[(size_t)r*V + n] = acc[mf][nf][cidx] + vb[n];
      }
}

__global__ void pgen_kernel(const float* __restrict__ whv, const float* __restrict__ wsv,
                            const float* __restrict__ wxv){
  int b=blockIdx.x;
  __shared__ float sm[256];
  float s=0.f;
  for (int e=threadIdx.x;e<E;e+=256) s+=g_context[b*E+e]*whv[e];
  for (int h=threadIdx.x;h<H;h+=256) s+=g_ht[b*H+h]*wsv[h];
  if (threadIdx.x<EMB) s+=g_embed[b*EMB+threadIdx.x]*wxv[threadIdx.x];
  sm[threadIdx.x]=s; __syncthreads();
  for (int o=128;o>0;o>>=1){ if(threadIdx.x<o) sm[threadIdx.x]+=sm[threadIdx.x+o]; __syncthreads(); }
  if (threadIdx.x==0) g_pgen[b]=1.f/(1.f+expf(-sm[0]));
}

__global__ void vocab_out_kernel(float* __restrict__ out){
  int b=blockIdx.x;
  __shared__ float sm[256];
  const float* l = &g_logits[(size_t)b*V];
  float m=-1e30f;
  for (int v=threadIdx.x;v<V;v+=256) m=fmaxf(m,l[v]);
  sm[threadIdx.x]=m; __syncthreads();
  for (int o=128;o>0;o>>=1){ if(threadIdx.x<o) sm[threadIdx.x]=fmaxf(sm[threadIdx.x],sm[threadIdx.x+o]); __syncthreads(); }
  m=sm[0]; __syncthreads();
  float s=0.f;
  for (int v=threadIdx.x;v<V;v+=256) s+=expf(l[v]-m);
  sm[threadIdx.x]=s; __syncthreads();
  for (int o=128;o>0;o>>=1){ if(threadIdx.x<o) sm[threadIdx.x]+=sm[threadIdx.x+o]; __syncthreads(); }
  float scale = g_pgen[b]/sm[0];
  for (int v=threadIdx.x;v<V;v+=256) out[(size_t)b*V+v]=expf(l[v]-m)*scale;
}

__global__ void scatter_kernel(const int* __restrict__ enc_inputs, float* __restrict__ out){
  int b=blockIdx.x;
  float om = 1.f - g_pgen[b];
  for (int s=threadIdx.x;s<S;s+=256){
    int tok = enc_inputs[b*S+s];
    atomicAdd(&out[(size_t)b*V+tok], om*g_energy[b*S+s]);
  }
}

// ---------------- launch ----------------
extern "C" void kernel_launch(void* const* d_in, const int* in_sizes, int n_in,
                              void* d_out, int out_size){
  const float* enc_out     = (const float*)d_in[0];
  const float* h0          = (const float*)d_in[1];
  const float* c0          = (const float*)d_in[2];
  const int*   dec_input   = (const int*)  d_in[3];
  const int*   enc_inputs  = (const int*)  d_in[4];
  const float* embed_table = (const float*)d_in[5];
  const float* attn_wh_w   = (const float*)d_in[6];
  const float* attn_wh_b   = (const float*)d_in[7];
  const float* attn_ws_w   = (const float*)d_in[8];
  const float* attn_ws_b   = (const float*)d_in[9];
  const float* attn_v      = (const float*)d_in[10];
  const float* lstm_w_ih   = (const float*)d_in[11];
  const float* lstm_w_hh   = (const float*)d_in[12];
  const float* lstm_b_ih   = (const float*)d_in[13];
  const float* lstm_b_hh   = (const float*)d_in[14];
  const float* wh_vec      = (const float*)d_in[15];
  const float* ws_vec      = (const float*)d_in[16];
  const float* wx_vec      = (const float*)d_in[17];
  const float* v_w         = (const float*)d_in[18];
  const float* v_b         = (const float*)d_in[19];
  float* out = (float*)d_out;

  // host-side attribute set (not a stream op; capture-safe)
  (void)cudaFuncSetAttribute(energy_gemm_kernel,
      cudaFuncAttributeMaxDynamicSharedMemorySize, EG_SMEM);

  conv_whw_kernel<<<256,256>>>(attn_wh_w);                                        // 0
  ws_app_kernel<<<B,256>>>(h0, attn_ws_w, attn_ws_b);                             // 1
  embed_kernel<<<B,256>>>(dec_input, embed_table);                                // 2
  energy_gemm_kernel<<<dim3(H/128, BS/128),256,EG_SMEM>>>(enc_out, attn_wh_b, attn_v); // 3 (profiled)
  zero_kernel<<<256,256>>>();                                                     // 4
  attn_softmax_kernel<<<B,256>>>();                                               // 5
  context_kernel<<<dim3(B,16),256>>>(enc_out);
  gates_kernel<<<dim3(32,8),256>>>(lstm_w_ih, lstm_w_hh, h0);
  lstm_kernel<<<B,H>>>(c0, lstm_b_ih, lstm_b_hh, out);
  logits_gemm_kernel<<<(V+127)/128,256>>>(v_w, v_b);
  pgen_kernel<<<B,256>>>(wh_vec, ws_vec, wx_vec);
  vocab_out_kernel<<<B,256>>>(out);
  scatter_kernel<<<B,256>>>(enc_inputs, out);
}